// round 5
// baseline (speedup 1.0000x reference)
#include <cuda_runtime.h>
#include <cuda_bf16.h>
#include <cstdint>
#include <math.h>

// Problem constants
#define ROWS 4096        // B*S
#define DIM  2048        // D
#define PD   8192        // P*D
#define NLAYERS 2
#define LN_EPS 1e-5f

// ---------------------------------------------------------------------------
// Device scratch (allocation-free rule: __device__ globals)
// ---------------------------------------------------------------------------
__device__ float g_h  [ROWS * DIM];
__device__ float g_t1 [ROWS * DIM];
__device__ float g_t2 [ROWS * DIM];
__device__ float g_w  [DIM * DIM];
__device__ float g_bias[DIM];
__device__ float g_mod[2 * DIM];
// bf16 split packs (K tripled)
__device__ __nv_bfloat16 g_actA [(size_t)ROWS * 3 * DIM];   // activations [M, 3D]
__device__ __nv_bfloat16 g_wp0  [(size_t)DIM * 3 * DIM];    // weight pack A
__device__ __nv_bfloat16 g_wp1  [(size_t)DIM * 3 * DIM];    // weight pack B
__device__ __nv_bfloat16 g_foldA[(size_t)DIM * 3 * PD];     // fold GEMM A'
__device__ __nv_bfloat16 g_foldB[(size_t)DIM * 3 * PD];     // fold GEMM B'

// ---------------------------------------------------------------------------
// PTX helpers (compute_103-safe: cp.async / ldmatrix / mma.sync only)
// ---------------------------------------------------------------------------
__device__ __forceinline__ uint32_t smem_u32(const void* p) {
    uint32_t a;
    asm("{ .reg .u64 t; cvta.to.shared.u64 t, %1; cvt.u32.u64 %0, t; }"
        : "=r"(a) : "l"(p));
    return a;
}
__device__ __forceinline__ void ldsm_x4(uint32_t& r0, uint32_t& r1,
                                        uint32_t& r2, uint32_t& r3,
                                        uint32_t addr) {
    asm volatile("ldmatrix.sync.aligned.m8n8.x4.shared.b16 {%0,%1,%2,%3}, [%4];"
                 : "=r"(r0), "=r"(r1), "=r"(r2), "=r"(r3) : "r"(addr));
}
__device__ __forceinline__ void mma16816(float* c,
                                         uint32_t a0, uint32_t a1, uint32_t a2, uint32_t a3,
                                         uint32_t b0, uint32_t b1) {
    asm volatile(
        "mma.sync.aligned.m16n8k16.row.col.f32.bf16.bf16.f32 "
        "{%0,%1,%2,%3}, {%4,%5,%6,%7}, {%8,%9}, {%0,%1,%2,%3};"
        : "+f"(c[0]), "+f"(c[1]), "+f"(c[2]), "+f"(c[3])
        : "r"(a0), "r"(a1), "r"(a2), "r"(a3), "r"(b0), "r"(b1));
}

// ---------------------------------------------------------------------------
// bf16 tensor-core GEMM: C[M,N] = A'[M,Kp] . B'[N,Kp]^T (+bias)
// CTA tile 128(M) x 256(N), BK=64 (128B swizzled rows), double-buffered
// cp.async, 8 warps each owning a 64x64 tile (MMA:ldsm = 4:1).
// ---------------------------------------------------------------------------
#define BM_T 128
#define BN_T 256
#define STAGE_BYTES (BM_T * 128 + BN_T * 128)   // 49152
#define GEMM_SMEM (2 * STAGE_BYTES + 1024)

__device__ __forceinline__ void load_tiles(uint32_t adst, uint32_t bdst,
                                           const char* Ag, const char* Bg,
                                           size_t rstride, int tid) {
    // A tile: 128 rows x 128B = 1024 16B chunks (4/thread)
    #pragma unroll
    for (int j = 0; j < 4; j++) {
        int c = tid + 256 * j;
        int r = c >> 3;
        int c16 = c & 7;
        uint32_t boff = (uint32_t)(r * 128 + c16 * 16);
        uint32_t sw = boff ^ ((boff >> 3) & 0x70);
        const char* ga = Ag + (size_t)r * rstride + (size_t)(c16 * 16);
        asm volatile("cp.async.ca.shared.global [%0], [%1], 16;"
                     :: "r"(adst + sw), "l"(ga) : "memory");
    }
    // B tile: 256 rows x 128B = 2048 16B chunks (8/thread)
    #pragma unroll
    for (int j = 0; j < 8; j++) {
        int c = tid + 256 * j;
        int r = c >> 3;
        int c16 = c & 7;
        uint32_t boff = (uint32_t)(r * 128 + c16 * 16);
        uint32_t sw = boff ^ ((boff >> 3) & 0x70);
        const char* gb = Bg + (size_t)r * rstride + (size_t)(c16 * 16);
        asm volatile("cp.async.ca.shared.global [%0], [%1], 16;"
                     :: "r"(bdst + sw), "l"(gb) : "memory");
    }
}

__global__ __launch_bounds__(256, 1) void gemm_mma(
    const __nv_bfloat16* __restrict__ A,   // [M, Kp] row-major
    const __nv_bfloat16* __restrict__ B,   // [N, Kp] row-major
    const float* __restrict__ bias,        // [N] or null
    float* __restrict__ C, int M, int N, int Kp)
{
    extern __shared__ char dsm[];
    const int tid = threadIdx.x;
    uint32_t sb = smem_u32(dsm);
    uint32_t ab = (sb + 1023u) & ~1023u;
    const uint32_t tA[2] = {ab,               ab + STAGE_BYTES};
    const uint32_t tB[2] = {ab + BM_T * 128,  ab + STAGE_BYTES + BM_T * 128};

    const int w = tid >> 5, lane = tid & 31;
    const int wm = (w >> 2) * 64;        // warp row base: 0 / 64
    const int wn = (w & 3) * 64;         // warp col base: 0/64/128/192

    // ldmatrix lane geometry (validated in R3)
    const int a_r  = (lane & 15);
    const int a_cs = (lane >> 4) << 4;
    const int b_r  = (((lane >> 4) & 1) << 3) | (lane & 7);
    const int b_cs = ((lane >> 3) & 1) << 4;

    float acc[4][8][4];
    #pragma unroll
    for (int i = 0; i < 4; i++)
        #pragma unroll
        for (int j = 0; j < 8; j++)
            #pragma unroll
            for (int q = 0; q < 4; q++) acc[i][j][q] = 0.f;

    const char* Ag = (const char*)(A + (size_t)blockIdx.y * BM_T * Kp);
    const char* Bg = (const char*)(B + (size_t)blockIdx.x * BN_T * Kp);
    const size_t rstride = (size_t)Kp * 2;
    const int nit = Kp >> 6;

    load_tiles(tA[0], tB[0], Ag, Bg, rstride, tid);
    asm volatile("cp.async.commit_group;" ::: "memory");

    for (int i = 0; i < nit; i++) {
        const int cur = i & 1, nxt = cur ^ 1;
        if (i + 1 < nit) {
            load_tiles(tA[nxt], tB[nxt],
                       Ag + (size_t)(i + 1) * 128, Bg + (size_t)(i + 1) * 128,
                       rstride, tid);
            asm volatile("cp.async.commit_group;" ::: "memory");
            asm volatile("cp.async.wait_group 1;" ::: "memory");
        } else {
            asm volatile("cp.async.wait_group 0;" ::: "memory");
        }
        __syncthreads();

        #pragma unroll
        for (int s = 0; s < 4; s++) {
            uint32_t af[4][4], bf[4][4];
            #pragma unroll
            for (int mt = 0; mt < 4; mt++) {
                int r = wm + mt * 16 + a_r;
                uint32_t addr = tA[cur] + r * 128 +
                                (uint32_t)((s * 32 + a_cs) ^ ((r & 7) << 4));
                ldsm_x4(af[mt][0], af[mt][1], af[mt][2], af[mt][3], addr);
            }
            #pragma unroll
            for (int nt2 = 0; nt2 < 4; nt2++) {
                int r = wn + nt2 * 16 + b_r;
                uint32_t addr = tB[cur] + r * 128 +
                                (uint32_t)((s * 32 + b_cs) ^ ((r & 7) << 4));
                ldsm_x4(bf[nt2][0], bf[nt2][1], bf[nt2][2], bf[nt2][3], addr);
            }
            #pragma unroll
            for (int mt = 0; mt < 4; mt++)
                #pragma unroll
                for (int nt = 0; nt < 8; nt++)
                    mma16816(acc[mt][nt],
                             af[mt][0], af[mt][1], af[mt][2], af[mt][3],
                             bf[nt >> 1][(nt & 1) * 2],
                             bf[nt >> 1][(nt & 1) * 2 + 1]);
        }
        __syncthreads();
    }

    // Epilogue: bias + store
    const int g = lane >> 2, t = lane & 3;
    #pragma unroll
    for (int mt = 0; mt < 4; mt++) {
        int row0 = blockIdx.y * BM_T + wm + mt * 16 + g;
        #pragma unroll
        for (int nt = 0; nt < 8; nt++) {
            int col = blockIdx.x * BN_T + wn + nt * 8 + 2 * t;
            float bx = 0.f, by = 0.f;
            if (bias) { bx = bias[col]; by = bias[col + 1]; }
            float2 o0, o1;
            o0.x = acc[mt][nt][0] + bx; o0.y = acc[mt][nt][1] + by;
            o1.x = acc[mt][nt][2] + bx; o1.y = acc[mt][nt][3] + by;
            *(float2*)&C[(size_t)row0 * N + col]       = o0;
            *(float2*)&C[(size_t)(row0 + 8) * N + col] = o1;
        }
    }
}

// ---------------------------------------------------------------------------
// Split-pack helpers: A' = [hi | hi | lo], B' = [hi | lo | hi]
// (A'.B'^T = hi.hi + hi.lo + lo.hi per K-third)
// ---------------------------------------------------------------------------
__device__ __forceinline__ void packA4(__nv_bfloat16* P, int m, int k, int K, float4 v) {
    union { __nv_bfloat16 b[4]; uint2 u; } H, L;
    H.b[0] = __float2bfloat16(v.x); H.b[1] = __float2bfloat16(v.y);
    H.b[2] = __float2bfloat16(v.z); H.b[3] = __float2bfloat16(v.w);
    L.b[0] = __float2bfloat16(v.x - __bfloat162float(H.b[0]));
    L.b[1] = __float2bfloat16(v.y - __bfloat162float(H.b[1]));
    L.b[2] = __float2bfloat16(v.z - __bfloat162float(H.b[2]));
    L.b[3] = __float2bfloat16(v.w - __bfloat162float(H.b[3]));
    size_t b = (size_t)m * 3 * K + k;
    *(uint2*)&P[b]         = H.u;
    *(uint2*)&P[b + K]     = H.u;
    *(uint2*)&P[b + 2 * K] = L.u;
}

__global__ void packA_kernel(const float* __restrict__ X,
                             __nv_bfloat16* __restrict__ P, int Mn, int K) {
    int i4 = blockIdx.x * blockDim.x + threadIdx.x;
    int tot = Mn * (K / 4);
    if (i4 < tot) {
        float4 v = ((const float4*)X)[i4];
        int kq = K / 4;
        int m = i4 / kq, k = (i4 - m * kq) * 4;
        packA4(P, m, k, K, v);
    }
}

// B' pack with transpose: input W [K,N] row-major -> P [N, 3K]
__global__ void packB_kernel(const float* __restrict__ W,
                             __nv_bfloat16* __restrict__ P, int K, int N) {
    __shared__ float tile[32][33];
    int n0 = blockIdx.x * 32, k0 = blockIdx.y * 32;
    int tx = threadIdx.x, ty = threadIdx.y;   // 32 x 8
    #pragma unroll
    for (int j = 0; j < 32; j += 8)
        tile[ty + j][tx] = W[(size_t)(k0 + ty + j) * N + n0 + tx];
    __syncthreads();
    #pragma unroll
    for (int j = 0; j < 32; j += 8) {
        int n = n0 + ty + j;
        int k = k0 + tx;
        float v = tile[tx][ty + j];            // W[k][n]
        __nv_bfloat16 hi = __float2bfloat16(v);
        __nv_bfloat16 lo = __float2bfloat16(v - __bfloat162float(hi));
        size_t b = (size_t)n * 3 * K;
        P[b + k]         = hi;
        P[b + K + k]     = lo;
        P[b + 2 * K + k] = hi;
    }
}

// ---------------------------------------------------------------------------
// Superposition combine (+ fused activation pack)
// ---------------------------------------------------------------------------
__global__ void combine_kernel(const float* __restrict__ za,
                               const float* __restrict__ zp,
                               float* __restrict__ h,
                               __nv_bfloat16* __restrict__ P) {
    int i4 = blockIdx.x * blockDim.x + threadIdx.x;
    const int tot = ROWS * DIM / 4;
    if (i4 >= tot) return;
    float4 a = ((const float4*)za)[i4];
    float4 p = ((const float4*)zp)[i4];
    float4 r;
    {
        float amp, ph, s, c;
        amp = 1.f / (1.f + __expf(-a.x)); ph = tanhf(p.x) * 3.14159265358979323846f;
        sincosf(ph, &s, &c); r.x = (c + s) * amp;
        amp = 1.f / (1.f + __expf(-a.y)); ph = tanhf(p.y) * 3.14159265358979323846f;
        sincosf(ph, &s, &c); r.y = (c + s) * amp;
        amp = 1.f / (1.f + __expf(-a.z)); ph = tanhf(p.z) * 3.14159265358979323846f;
        sincosf(ph, &s, &c); r.z = (c + s) * amp;
        amp = 1.f / (1.f + __expf(-a.w)); ph = tanhf(p.w) * 3.14159265358979323846f;
        sincosf(ph, &s, &c); r.w = (c + s) * amp;
    }
    ((float4*)h)[i4] = r;
    const int kq = DIM / 4;
    int m = i4 / kq, k = (i4 - m * kq) * 4;
    packA4(P, m, k, DIM, r);
}

// ---------------------------------------------------------------------------
// Folded entanglement bias: out[n] = sum_k eb[k]*Wprj[k,n] + pb[n]
// ---------------------------------------------------------------------------
__global__ __launch_bounds__(256) void bent_kernel(
    const float* __restrict__ eb, const float* __restrict__ W,
    const float* __restrict__ pb, float* __restrict__ out) {
    __shared__ float red[256];
    const int col = blockIdx.x * 32 + (threadIdx.x & 31);
    const int seg = threadIdx.x >> 5;
    float s = 0.f;
    const int k0 = seg * (PD / 8);
    #pragma unroll 4
    for (int k = k0; k < k0 + PD / 8; k++)
        s = fmaf(eb[k], W[(size_t)k * DIM + col], s);
    red[threadIdx.x] = s;
    __syncthreads();
    if (seg == 0) {
        float t = s;
        #pragma unroll
        for (int i = 1; i < 8; i++) t += red[i * 32 + threadIdx.x];
        out[col] = t + pb[col];
    }
}

// ---------------------------------------------------------------------------
// Pathway modulation + folded bias
// ---------------------------------------------------------------------------
__global__ void modbeff_kernel(const float* __restrict__ phase,
                               const float* __restrict__ pb,
                               float* __restrict__ mod,
                               float* __restrict__ beff) {
    int f = blockIdx.x * blockDim.x + threadIdx.x;
    if (f < DIM) {
        float s0, c0, s1, c1;
        sincosf(phase[f],       &s0, &c0);
        sincosf(phase[DIM + f], &s1, &c1);
        float m0 = c0 + s0, m1 = c1 + s1;
        mod[f] = m0;
        mod[DIM + f] = m1;
        beff[f] = pb[f] * m0 + pb[DIM + f] * m1;
    }
}

__global__ void weff_kernel(const float* __restrict__ pw,
                            const float* __restrict__ mod,
                            float* __restrict__ W) {
    int i = blockIdx.x * blockDim.x + threadIdx.x;
    const int NQ = DIM * DIM / 4;
    if (i < NQ) {
        const float4* p0 = (const float4*)pw;
        const float4* p1 = (const float4*)(pw + (size_t)DIM * DIM);
        int f4 = i & (DIM / 4 - 1);
        float4 m0 = ((const float4*)mod)[f4];
        float4 m1 = ((const float4*)(mod + DIM))[f4];
        float4 a = p0[i], b = p1[i], r;
        r.x = fmaf(a.x, m0.x, b.x * m1.x);
        r.y = fmaf(a.y, m0.y, b.y * m1.y);
        r.z = fmaf(a.z, m0.z, b.z * m1.z);
        r.w = fmaf(a.w, m0.w, b.w * m1.w);
        ((float4*)W)[i] = r;
    }
}

// ---------------------------------------------------------------------------
// Fused residual + LayerNorm (+ optional activation pack)
// ---------------------------------------------------------------------------
__global__ __launch_bounds__(256) void add_ln_kernel(
    const float* __restrict__ H, const float* __restrict__ T,
    const float* __restrict__ g, const float* __restrict__ b,
    float* __restrict__ O, __nv_bfloat16* __restrict__ P) {
    __shared__ float sv[DIM];
    __shared__ float rs[8], rss[8];
    __shared__ float stats[2];

    const int row = blockIdx.x;
    const float4* H4 = (const float4*)(H + (size_t)row * DIM);
    const float4* T4 = (const float4*)(T + (size_t)row * DIM);
    float4* O4 = (float4*)(O + (size_t)row * DIM);

    float s = 0.f, ss = 0.f;
    #pragma unroll
    for (int i = threadIdx.x; i < DIM / 4; i += 256) {
        float4 hv = H4[i], tv = T4[i];
        float4 v;
        v.x = hv.x + tv.x; v.y = hv.y + tv.y;
        v.z = hv.z + tv.z; v.w = hv.w + tv.w;
        ((float4*)sv)[i] = v;
        s  += v.x + v.y + v.z + v.w;
        ss += v.x*v.x + v.y*v.y + v.z*v.z + v.w*v.w;
    }
    #pragma unroll
    for (int o = 16; o; o >>= 1) {
        s  += __shfl_xor_sync(0xffffffffu, s, o);
        ss += __shfl_xor_sync(0xffffffffu, ss, o);
    }
    if ((threadIdx.x & 31) == 0) {
        rs [threadIdx.x >> 5] = s;
        rss[threadIdx.x >> 5] = ss;
    }
    __syncthreads();
    if (threadIdx.x == 0) {
        float S = 0.f, SS = 0.f;
        #pragma unroll
        for (int i = 0; i < 8; i++) { S += rs[i]; SS += rss[i]; }
        float mean = S / DIM;
        float var  = SS / DIM - mean * mean;
        stats[0] = mean;
        stats[1] = rsqrtf(var + LN_EPS);
    }
    __syncthreads();
    const float mean = stats[0], rstd = stats[1];

    #pragma unroll
    for (int i = threadIdx.x; i < DIM / 4; i += 256) {
        float4 v = ((const float4*)sv)[i];
        float4 gv = ((const float4*)g)[i];
        float4 bv = ((const float4*)b)[i];
        float4 o;
        o.x = (v.x - mean) * rstd * gv.x + bv.x;
        o.y = (v.y - mean) * rstd * gv.y + bv.y;
        o.z = (v.z - mean) * rstd * gv.z + bv.z;
        o.w = (v.w - mean) * rstd * gv.w + bv.w;
        O4[i] = o;
        if (P) packA4(P, row, i * 4, DIM, o);
    }
}

// ---------------------------------------------------------------------------
// kernel_launch
// ---------------------------------------------------------------------------
static void launch_gemm(const __nv_bfloat16* A, const __nv_bfloat16* B,
                        const float* bias, float* C, int M, int N, int Kp) {
    dim3 grid(N / BN_T, M / BM_T);
    gemm_mma<<<grid, 256, GEMM_SMEM>>>(A, B, bias, C, M, N, Kp);
}

extern "C" void kernel_launch(void* const* d_in, const int* in_sizes, int n_in,
                              void* d_out, int out_size)
{
    const float* x      = (const float*)d_in[0];
    const float* amp_w  = (const float*)d_in[1];
    const float* amp_b  = (const float*)d_in[2];
    const float* ph_w   = (const float*)d_in[3];
    const float* ph_b   = (const float*)d_in[4];
    const float* ent_w  = (const float*)d_in[5];   // [L, D, P*D]
    const float* ent_b  = (const float*)d_in[6];   // [L, P*D]
    const float* ent_pw = (const float*)d_in[7];   // [L, P*D, D]
    const float* ent_pb = (const float*)d_in[8];   // [L, D]
    const float* path_w = (const float*)d_in[9];   // [L, PW, D, D]
    const float* path_b = (const float*)d_in[10];  // [L, PW, D]
    const float* phase  = (const float*)d_in[11];  // [L, PW, D]
    const float* ln3_g  = (const float*)d_in[12];
    const float* ln3_b  = (const float*)d_in[13];
    const float* ln4_g  = (const float*)d_in[14];
    const float* ln4_b  = (const float*)d_in[15];
    float* out = (float*)d_out;

    cudaFuncSetAttribute(gemm_mma, cudaFuncAttributeMaxDynamicSharedMemorySize,
                         GEMM_SMEM);

    float *h, *t1, *t2, *w, *bias, *mod;
    __nv_bfloat16 *actA, *wp0, *wp1, *fA, *fB;
    cudaGetSymbolAddress((void**)&h,    g_h);
    cudaGetSymbolAddress((void**)&t1,   g_t1);
    cudaGetSymbolAddress((void**)&t2,   g_t2);
    cudaGetSymbolAddress((void**)&w,    g_w);
    cudaGetSymbolAddress((void**)&bias, g_bias);
    cudaGetSymbolAddress((void**)&mod,  g_mod);
    cudaGetSymbolAddress((void**)&actA, g_actA);
    cudaGetSymbolAddress((void**)&wp0,  g_wp0);
    cudaGetSymbolAddress((void**)&wp1,  g_wp1);
    cudaGetSymbolAddress((void**)&fA,   g_foldA);
    cudaGetSymbolAddress((void**)&fB,   g_foldB);

    const int n = ROWS * DIM;

    // ---- Superposition layer ----
    packA_kernel<<<(n / 4 + 255) / 256, 256>>>(x, actA, ROWS, DIM);
    packB_kernel<<<dim3(DIM / 32, DIM / 32), dim3(32, 8)>>>(amp_w, wp0, DIM, DIM);
    packB_kernel<<<dim3(DIM / 32, DIM / 32), dim3(32, 8)>>>(ph_w,  wp1, DIM, DIM);
    launch_gemm(actA, wp0, amp_b, t1, ROWS, DIM, 3 * DIM);
    launch_gemm(actA, wp1, ph_b,  t2, ROWS, DIM, 3 * DIM);
    combine_kernel<<<(n / 4 + 255) / 256, 256>>>(t1, t2, h, actA);

    // ---- Layers ----
    for (int l = 0; l < NLAYERS; l++) {
        const float* Wexp = ent_w  + (size_t)l * DIM * PD;
        const float* Wprj = ent_pw + (size_t)l * PD * DIM;

        // Fold entanglement: w = Wexp @ Wprj (tensor cores)
        packA_kernel<<<(DIM * PD / 4 + 255) / 256, 256>>>(Wexp, fA, DIM, PD);
        packB_kernel<<<dim3(DIM / 32, PD / 32), dim3(32, 8)>>>(Wprj, fB, PD, DIM);
        launch_gemm(fA, fB, nullptr, w, DIM, DIM, 3 * PD);
        bent_kernel<<<DIM / 32, 256>>>(ent_b + (size_t)l * PD, Wprj,
                                       ent_pb + (size_t)l * DIM, bias);

        // ent apply: t1 = h @ w + bias ; h = LN(h + t1)  (act pack intact)
        packB_kernel<<<dim3(DIM / 32, DIM / 32), dim3(32, 8)>>>(w, wp0, DIM, DIM);
        launch_gemm(actA, wp0, bias, t1, ROWS, DIM, 3 * DIM);
        add_ln_kernel<<<ROWS, 256>>>(h, t1,
                                     ln3_g + (size_t)l * DIM,
                                     ln3_b + (size_t)l * DIM, h, actA);

        // Fold interference pathways into one GEMM
        modbeff_kernel<<<DIM / 256, 256>>>(phase  + (size_t)l * 2 * DIM,
                                           path_b + (size_t)l * 2 * DIM,
                                           mod, bias);
        weff_kernel<<<(DIM * DIM / 4 + 255) / 256, 256>>>(
            path_w + (size_t)l * 2 * DIM * DIM, mod, w);
        packB_kernel<<<dim3(DIM / 32, DIM / 32), dim3(32, 8)>>>(w, wp1, DIM, DIM);
        launch_gemm(actA, wp1, bias, t1, ROWS, DIM, 3 * DIM);
        add_ln_kernel<<<ROWS, 256>>>(h, t1,
                                     ln4_g + (size_t)l * DIM,
                                     ln4_b + (size_t)l * DIM,
                                     (l == NLAYERS - 1) ? out : h,
                                     (l == NLAYERS - 1) ? (__nv_bfloat16*)nullptr
                                                        : actA);
    }
}

// round 7
// speedup vs baseline: 1.2939x; 1.2939x over previous
#include <cuda_runtime.h>
#include <cuda_bf16.h>
#include <cstdint>
#include <math.h>

// Problem constants
#define ROWS 4096        // B*S
#define DIM  2048        // D
#define PD   8192        // P*D
#define NLAYERS 2
#define LN_EPS 1e-5f

// ---------------------------------------------------------------------------
// Device scratch (allocation-free rule: __device__ globals)
// ---------------------------------------------------------------------------
__device__ float g_h  [ROWS * DIM];
__device__ float g_t1 [ROWS * DIM];
__device__ float g_t2 [ROWS * DIM];
__device__ float g_w  [DIM * DIM];
__device__ float g_bias[DIM];
__device__ float g_mod[2 * DIM];
// bf16 split packs (K tripled)
__device__ __nv_bfloat16 g_actA [(size_t)ROWS * 3 * DIM];
__device__ __nv_bfloat16 g_wp0  [(size_t)DIM * 3 * DIM];
__device__ __nv_bfloat16 g_wp1  [(size_t)DIM * 3 * DIM];
__device__ __nv_bfloat16 g_foldA[(size_t)DIM * 3 * PD];
__device__ __nv_bfloat16 g_foldB[(size_t)DIM * 3 * PD];

// ---------------------------------------------------------------------------
// PTX helpers (compute_103-safe: cp.async / ldmatrix / mma.sync only)
// ---------------------------------------------------------------------------
__device__ __forceinline__ uint32_t smem_u32(const void* p) {
    uint32_t a;
    asm("{ .reg .u64 t; cvta.to.shared.u64 t, %1; cvt.u32.u64 %0, t; }"
        : "=r"(a) : "l"(p));
    return a;
}
__device__ __forceinline__ void ldsm_x4(uint32_t& r0, uint32_t& r1,
                                        uint32_t& r2, uint32_t& r3,
                                        uint32_t addr) {
    asm volatile("ldmatrix.sync.aligned.m8n8.x4.shared.b16 {%0,%1,%2,%3}, [%4];"
                 : "=r"(r0), "=r"(r1), "=r"(r2), "=r"(r3) : "r"(addr));
}
__device__ __forceinline__ void mma16816(float* c,
                                         uint32_t a0, uint32_t a1, uint32_t a2, uint32_t a3,
                                         uint32_t b0, uint32_t b1) {
    asm volatile(
        "mma.sync.aligned.m16n8k16.row.col.f32.bf16.bf16.f32 "
        "{%0,%1,%2,%3}, {%4,%5,%6,%7}, {%8,%9}, {%0,%1,%2,%3};"
        : "+f"(c[0]), "+f"(c[1]), "+f"(c[2]), "+f"(c[3])
        : "r"(a0), "r"(a1), "r"(a2), "r"(a3), "r"(b0), "r"(b1));
}

// ---------------------------------------------------------------------------
// bf16 tensor-core GEMM: C[M,N] = A'[M,Kp] . B'[N,Kp]^T (+bias)
// CTA tile 128x128, 4 warps x (64x64) [MMA:ldsm = 4:1], BK=64,
// 3-stage cp.async.cg pipeline -> 2 CTAs/SM for cross-sync overlap.
// ---------------------------------------------------------------------------
#define NSTAGE 3
#define STAGE_BYTES (2 * 128 * 128)             // A 16KB + B 16KB
#define GEMM_SMEM (NSTAGE * STAGE_BYTES + 1024)

__device__ __forceinline__ void load_tiles(uint32_t adst, uint32_t bdst,
                                           const char* Ag, const char* Bg,
                                           size_t rstride, int tid) {
    // A: 128 rows x 128B = 1024 chunks (8/thread); B: same.
    #pragma unroll
    for (int j = 0; j < 8; j++) {
        int c = tid + 128 * j;
        int r = c >> 3;
        int c16 = c & 7;
        uint32_t boff = (uint32_t)(r * 128 + c16 * 16);
        uint32_t sw = boff ^ ((boff >> 3) & 0x70);
        const char* ga = Ag + (size_t)r * rstride + (size_t)(c16 * 16);
        const char* gb = Bg + (size_t)r * rstride + (size_t)(c16 * 16);
        asm volatile("cp.async.cg.shared.global [%0], [%1], 16;"
                     :: "r"(adst + sw), "l"(ga) : "memory");
        asm volatile("cp.async.cg.shared.global [%0], [%1], 16;"
                     :: "r"(bdst + sw), "l"(gb) : "memory");
    }
}

__global__ __launch_bounds__(128, 2) void gemm_mma(
    const __nv_bfloat16* __restrict__ A,   // [M, Kp] row-major
    const __nv_bfloat16* __restrict__ B,   // [N, Kp] row-major
    const float* __restrict__ bias,        // [N] or null
    float* __restrict__ C, int M, int N, int Kp)
{
    extern __shared__ char dsm[];
    const int tid = threadIdx.x;
    uint32_t sb = smem_u32(dsm);
    uint32_t ab = (sb + 1023u) & ~1023u;
    uint32_t tA[NSTAGE], tB[NSTAGE];
    #pragma unroll
    for (int s = 0; s < NSTAGE; s++) {
        tA[s] = ab + s * STAGE_BYTES;
        tB[s] = ab + s * STAGE_BYTES + 128 * 128;
    }

    const int w = tid >> 5, lane = tid & 31;
    const int wm = (w >> 1) * 64;        // warp row base: 0 / 64
    const int wn = (w & 1) * 64;         // warp col base: 0 / 64

    // ldmatrix lane geometry (validated R3/R4)
    const int a_r  = (lane & 15);
    const int a_cs = (lane >> 4) << 4;
    const int b_r  = (((lane >> 4) & 1) << 3) | (lane & 7);
    const int b_cs = ((lane >> 3) & 1) << 4;

    float acc[4][8][4];
    #pragma unroll
    for (int i = 0; i < 4; i++)
        #pragma unroll
        for (int j = 0; j < 8; j++)
            #pragma unroll
            for (int q = 0; q < 4; q++) acc[i][j][q] = 0.f;

    const char* Ag = (const char*)(A + (size_t)blockIdx.y * 128 * Kp);
    const char* Bg = (const char*)(B + (size_t)blockIdx.x * 128 * Kp);
    const size_t rstride = (size_t)Kp * 2;
    const int nit = Kp >> 6;

    // Prologue: fill stages 0 and 1
    load_tiles(tA[0], tB[0], Ag, Bg, rstride, tid);
    asm volatile("cp.async.commit_group;" ::: "memory");
    if (nit > 1) {
        load_tiles(tA[1], tB[1], Ag + 128, Bg + 128, rstride, tid);
    }
    asm volatile("cp.async.commit_group;" ::: "memory");

    int cur = 0;
    for (int i = 0; i < nit; i++) {
        asm volatile("cp.async.wait_group 1;" ::: "memory");
        __syncthreads();

        #pragma unroll
        for (int s = 0; s < 4; s++) {
            uint32_t af[4][4], bf[4][4];
            #pragma unroll
            for (int mt = 0; mt < 4; mt++) {
                int r = wm + mt * 16 + a_r;
                uint32_t addr = tA[cur] + r * 128 +
                                (uint32_t)((s * 32 + a_cs) ^ ((r & 7) << 4));
                ldsm_x4(af[mt][0], af[mt][1], af[mt][2], af[mt][3], addr);
            }
            #pragma unroll
            for (int nt2 = 0; nt2 < 4; nt2++) {
                int r = wn + nt2 * 16 + b_r;
                uint32_t addr = tB[cur] + r * 128 +
                                (uint32_t)((s * 32 + b_cs) ^ ((r & 7) << 4));
                ldsm_x4(bf[nt2][0], bf[nt2][1], bf[nt2][2], bf[nt2][3], addr);
            }
            #pragma unroll
            for (int mt = 0; mt < 4; mt++)
                #pragma unroll
                for (int nt = 0; nt < 8; nt++)
                    mma16816(acc[mt][nt],
                             af[mt][0], af[mt][1], af[mt][2], af[mt][3],
                             bf[nt >> 1][(nt & 1) * 2],
                             bf[nt >> 1][(nt & 1) * 2 + 1]);
        }
        __syncthreads();   // all warps done reading stage (i+2)%NSTAGE's buffer

        if (i + 2 < nit) {
            int nxt = (cur + 2) % NSTAGE;
            load_tiles(tA[nxt], tB[nxt],
                       Ag + (size_t)(i + 2) * 128, Bg + (size_t)(i + 2) * 128,
                       rstride, tid);
        }
        asm volatile("cp.async.commit_group;" ::: "memory");
        cur = (cur + 1) % NSTAGE;
    }

    // Epilogue: bias + store
    const int g = lane >> 2, t = lane & 3;
    #pragma unroll
    for (int mt = 0; mt < 4; mt++) {
        int row0 = blockIdx.y * 128 + wm + mt * 16 + g;
        #pragma unroll
        for (int nt = 0; nt < 8; nt++) {
            int col = blockIdx.x * 128 + wn + nt * 8 + 2 * t;
            float bx = 0.f, by = 0.f;
            if (bias) { bx = bias[col]; by = bias[col + 1]; }
            float2 o0, o1;
            o0.x = acc[mt][nt][0] + bx; o0.y = acc[mt][nt][1] + by;
            o1.x = acc[mt][nt][2] + bx; o1.y = acc[mt][nt][3] + by;
            *(float2*)&C[(size_t)row0 * N + col]       = o0;
            *(float2*)&C[(size_t)(row0 + 8) * N + col] = o1;
        }
    }
}

// ---------------------------------------------------------------------------
// Split-pack helpers: A' = [hi | hi | lo], B' = [hi | lo | hi]
// ---------------------------------------------------------------------------
__device__ __forceinline__ void packA4(__nv_bfloat16* P, int m, int k, int K, float4 v) {
    union { __nv_bfloat16 b[4]; uint2 u; } H, L;
    H.b[0] = __float2bfloat16(v.x); H.b[1] = __float2bfloat16(v.y);
    H.b[2] = __float2bfloat16(v.z); H.b[3] = __float2bfloat16(v.w);
    L.b[0] = __float2bfloat16(v.x - __bfloat162float(H.b[0]));
    L.b[1] = __float2bfloat16(v.y - __bfloat162float(H.b[1]));
    L.b[2] = __float2bfloat16(v.z - __bfloat162float(H.b[2]));
    L.b[3] = __float2bfloat16(v.w - __bfloat162float(H.b[3]));
    size_t b = (size_t)m * 3 * K + k;
    *(uint2*)&P[b]         = H.u;
    *(uint2*)&P[b + K]     = H.u;
    *(uint2*)&P[b + 2 * K] = L.u;
}

__global__ void packA_kernel(const float* __restrict__ X,
                             __nv_bfloat16* __restrict__ P, int Mn, int K) {
    int i4 = blockIdx.x * blockDim.x + threadIdx.x;
    int tot = Mn * (K / 4);
    if (i4 < tot) {
        float4 v = ((const float4*)X)[i4];
        int kq = K / 4;
        int m = i4 / kq, k = (i4 - m * kq) * 4;
        packA4(P, m, k, K, v);
    }
}

// B' pack with transpose: input W [K,N] row-major -> P [N, 3K]
__global__ void packB_kernel(const float* __restrict__ W,
                             __nv_bfloat16* __restrict__ P, int K, int N) {
    __shared__ float tile[32][33];
    int n0 = blockIdx.x * 32, k0 = blockIdx.y * 32;
    int tx = threadIdx.x, ty = threadIdx.y;   // 32 x 8
    #pragma unroll
    for (int j = 0; j < 32; j += 8)
        tile[ty + j][tx] = W[(size_t)(k0 + ty + j) * N + n0 + tx];
    __syncthreads();
    #pragma unroll
    for (int j = 0; j < 32; j += 8) {
        int n = n0 + ty + j;
        int k = k0 + tx;
        float v = tile[tx][ty + j];            // W[k][n]
        __nv_bfloat16 hi = __float2bfloat16(v);
        __nv_bfloat16 lo = __float2bfloat16(v - __bfloat162float(hi));
        size_t b = (size_t)n * 3 * K;
        P[b + k]         = hi;
        P[b + K + k]     = lo;
        P[b + 2 * K + k] = hi;
    }
}

// ---------------------------------------------------------------------------
// Superposition combine (+ fused activation pack)
// ---------------------------------------------------------------------------
__global__ void combine_kernel(const float* __restrict__ za,
                               const float* __restrict__ zp,
                               float* __restrict__ h,
                               __nv_bfloat16* __restrict__ P) {
    int i4 = blockIdx.x * blockDim.x + threadIdx.x;
    const int tot = ROWS * DIM / 4;
    if (i4 >= tot) return;
    float4 a = ((const float4*)za)[i4];
    float4 p = ((const float4*)zp)[i4];
    float4 r;
    {
        float amp, ph, s, c;
        amp = 1.f / (1.f + __expf(-a.x)); ph = tanhf(p.x) * 3.14159265358979323846f;
        sincosf(ph, &s, &c); r.x = (c + s) * amp;
        amp = 1.f / (1.f + __expf(-a.y)); ph = tanhf(p.y) * 3.14159265358979323846f;
        sincosf(ph, &s, &c); r.y = (c + s) * amp;
        amp = 1.f / (1.f + __expf(-a.z)); ph = tanhf(p.z) * 3.14159265358979323846f;
        sincosf(ph, &s, &c); r.z = (c + s) * amp;
        amp = 1.f / (1.f + __expf(-a.w)); ph = tanhf(p.w) * 3.14159265358979323846f;
        sincosf(ph, &s, &c); r.w = (c + s) * amp;
    }
    ((float4*)h)[i4] = r;
    const int kq = DIM / 4;
    int m = i4 / kq, k = (i4 - m * kq) * 4;
    packA4(P, m, k, DIM, r);
}

// ---------------------------------------------------------------------------
// Folded entanglement bias: out[n] = sum_k eb[k]*Wprj[k,n] + pb[n]
// ---------------------------------------------------------------------------
__global__ __launch_bounds__(256) void bent_kernel(
    const float* __restrict__ eb, const float* __restrict__ W,
    const float* __restrict__ pb, float* __restrict__ out) {
    __shared__ float red[256];
    const int col = blockIdx.x * 32 + (threadIdx.x & 31);
    const int seg = threadIdx.x >> 5;
    float s = 0.f;
    const int k0 = seg * (PD / 8);
    #pragma unroll 4
    for (int k = k0; k < k0 + PD / 8; k++)
        s = fmaf(eb[k], W[(size_t)k * DIM + col], s);
    red[threadIdx.x] = s;
    __syncthreads();
    if (seg == 0) {
        float t = s;
        #pragma unroll
        for (int i = 1; i < 8; i++) t += red[i * 32 + threadIdx.x];
        out[col] = t + pb[col];
    }
}

// ---------------------------------------------------------------------------
// Pathway modulation + folded bias
// ---------------------------------------------------------------------------
__global__ void modbeff_kernel(const float* __restrict__ phase,
                               const float* __restrict__ pb,
                               float* __restrict__ mod,
                               float* __restrict__ beff) {
    int f = blockIdx.x * blockDim.x + threadIdx.x;
    if (f < DIM) {
        float s0, c0, s1, c1;
        sincosf(phase[f],       &s0, &c0);
        sincosf(phase[DIM + f], &s1, &c1);
        float m0 = c0 + s0, m1 = c1 + s1;
        mod[f] = m0;
        mod[DIM + f] = m1;
        beff[f] = pb[f] * m0 + pb[DIM + f] * m1;
    }
}

__global__ void weff_kernel(const float* __restrict__ pw,
                            const float* __restrict__ mod,
                            float* __restrict__ W) {
    int i = blockIdx.x * blockDim.x + threadIdx.x;
    const int NQ = DIM * DIM / 4;
    if (i < NQ) {
        const float4* p0 = (const float4*)pw;
        const float4* p1 = (const float4*)(pw + (size_t)DIM * DIM);
        int f4 = i & (DIM / 4 - 1);
        float4 m0 = ((const float4*)mod)[f4];
        float4 m1 = ((const float4*)(mod + DIM))[f4];
        float4 a = p0[i], b = p1[i], r;
        r.x = fmaf(a.x, m0.x, b.x * m1.x);
        r.y = fmaf(a.y, m0.y, b.y * m1.y);
        r.z = fmaf(a.z, m0.z, b.z * m1.z);
        r.w = fmaf(a.w, m0.w, b.w * m1.w);
        ((float4*)W)[i] = r;
    }
}

// ---------------------------------------------------------------------------
// Fused residual + LayerNorm (+ optional activation pack)
// ---------------------------------------------------------------------------
__global__ __launch_bounds__(256) void add_ln_kernel(
    const float* __restrict__ H, const float* __restrict__ T,
    const float* __restrict__ g, const float* __restrict__ b,
    float* __restrict__ O, __nv_bfloat16* __restrict__ P) {
    __shared__ float sv[DIM];
    __shared__ float rs[8], rss[8];
    __shared__ float stats[2];

    const int row = blockIdx.x;
    const float4* H4 = (const float4*)(H + (size_t)row * DIM);
    const float4* T4 = (const float4*)(T + (size_t)row * DIM);
    float4* O4 = (float4*)(O + (size_t)row * DIM);

    float s = 0.f, ss = 0.f;
    #pragma unroll
    for (int i = threadIdx.x; i < DIM / 4; i += 256) {
        float4 hv = H4[i], tv = T4[i];
        float4 v;
        v.x = hv.x + tv.x; v.y = hv.y + tv.y;
        v.z = hv.z + tv.z; v.w = hv.w + tv.w;
        ((float4*)sv)[i] = v;
        s  += v.x + v.y + v.z + v.w;
        ss += v.x*v.x + v.y*v.y + v.z*v.z + v.w*v.w;
    }
    #pragma unroll
    for (int o = 16; o; o >>= 1) {
        s  += __shfl_xor_sync(0xffffffffu, s, o);
        ss += __shfl_xor_sync(0xffffffffu, ss, o);
    }
    if ((threadIdx.x & 31) == 0) {
        rs [threadIdx.x >> 5] = s;
        rss[threadIdx.x >> 5] = ss;
    }
    __syncthreads();
    if (threadIdx.x == 0) {
        float S = 0.f, SS = 0.f;
        #pragma unroll
        for (int i = 0; i < 8; i++) { S += rs[i]; SS += rss[i]; }
        float mean = S / DIM;
        float var  = SS / DIM - mean * mean;
        stats[0] = mean;
        stats[1] = rsqrtf(var + LN_EPS);
    }
    __syncthreads();
    const float mean = stats[0], rstd = stats[1];

    #pragma unroll
    for (int i = threadIdx.x; i < DIM / 4; i += 256) {
        float4 v = ((const float4*)sv)[i];
        float4 gv = ((const float4*)g)[i];
        float4 bv = ((const float4*)b)[i];
        float4 o;
        o.x = (v.x - mean) * rstd * gv.x + bv.x;
        o.y = (v.y - mean) * rstd * gv.y + bv.y;
        o.z = (v.z - mean) * rstd * gv.z + bv.z;
        o.w = (v.w - mean) * rstd * gv.w + bv.w;
        O4[i] = o;
        if (P) packA4(P, row, i * 4, DIM, o);
    }
}

// ---------------------------------------------------------------------------
// kernel_launch
// ---------------------------------------------------------------------------
static void launch_gemm(const __nv_bfloat16* A, const __nv_bfloat16* B,
                        const float* bias, float* C, int M, int N, int Kp) {
    dim3 grid(N / 128, M / 128);
    gemm_mma<<<grid, 128, GEMM_SMEM>>>(A, B, bias, C, M, N, Kp);
}

extern "C" void kernel_launch(void* const* d_in, const int* in_sizes, int n_in,
                              void* d_out, int out_size)
{
    const float* x      = (const float*)d_in[0];
    const float* amp_w  = (const float*)d_in[1];
    const float* amp_b  = (const float*)d_in[2];
    const float* ph_w   = (const float*)d_in[3];
    const float* ph_b   = (const float*)d_in[4];
    const float* ent_w  = (const float*)d_in[5];   // [L, D, P*D]
    const float* ent_b  = (const float*)d_in[6];   // [L, P*D]
    const float* ent_pw = (const float*)d_in[7];   // [L, P*D, D]
    const float* ent_pb = (const float*)d_in[8];   // [L, D]
    const float* path_w = (const float*)d_in[9];   // [L, PW, D, D]
    const float* path_b = (const float*)d_in[10];  // [L, PW, D]
    const float* phase  = (const float*)d_in[11];  // [L, PW, D]
    const float* ln3_g  = (const float*)d_in[12];
    const float* ln3_b  = (const float*)d_in[13];
    const float* ln4_g  = (const float*)d_in[14];
    const float* ln4_b  = (const float*)d_in[15];
    float* out = (float*)d_out;

    cudaFuncSetAttribute(gemm_mma, cudaFuncAttributeMaxDynamicSharedMemorySize,
                         GEMM_SMEM);

    float *h, *t1, *t2, *w, *bias, *mod;
    __nv_bfloat16 *actA, *wp0, *wp1, *fA, *fB;
    cudaGetSymbolAddress((void**)&h,    g_h);
    cudaGetSymbolAddress((void**)&t1,   g_t1);
    cudaGetSymbolAddress((void**)&t2,   g_t2);
    cudaGetSymbolAddress((void**)&w,    g_w);
    cudaGetSymbolAddress((void**)&bias, g_bias);
    cudaGetSymbolAddress((void**)&mod,  g_mod);
    cudaGetSymbolAddress((void**)&actA, g_actA);
    cudaGetSymbolAddress((void**)&wp0,  g_wp0);
    cudaGetSymbolAddress((void**)&wp1,  g_wp1);
    cudaGetSymbolAddress((void**)&fA,   g_foldA);
    cudaGetSymbolAddress((void**)&fB,   g_foldB);

    const int n = ROWS * DIM;

    // ---- Superposition layer ----
    packA_kernel<<<(n / 4 + 255) / 256, 256>>>(x, actA, ROWS, DIM);
    packB_kernel<<<dim3(DIM / 32, DIM / 32), dim3(32, 8)>>>(amp_w, wp0, DIM, DIM);
    packB_kernel<<<dim3(DIM / 32, DIM / 32), dim3(32, 8)>>>(ph_w,  wp1, DIM, DIM);
    launch_gemm(actA, wp0, amp_b, t1, ROWS, DIM, 3 * DIM);
    launch_gemm(actA, wp1, ph_b,  t2, ROWS, DIM, 3 * DIM);
    combine_kernel<<<(n / 4 + 255) / 256, 256>>>(t1, t2, h, actA);

    // ---- Layers ----
    for (int l = 0; l < NLAYERS; l++) {
        const float* Wexp = ent_w  + (size_t)l * DIM * PD;
        const float* Wprj = ent_pw + (size_t)l * PD * DIM;

        // Fold entanglement: w = Wexp @ Wprj (tensor cores)
        packA_kernel<<<(DIM * PD / 4 + 255) / 256, 256>>>(Wexp, fA, DIM, PD);
        packB_kernel<<<dim3(DIM / 32, PD / 32), dim3(32, 8)>>>(Wprj, fB, PD, DIM);
        launch_gemm(fA, fB, nullptr, w, DIM, DIM, 3 * PD);
        bent_kernel<<<DIM / 32, 256>>>(ent_b + (size_t)l * PD, Wprj,
                                       ent_pb + (size_t)l * DIM, bias);

        // ent apply: t1 = h @ w + bias ; h = LN(h + t1)
        packB_kernel<<<dim3(DIM / 32, DIM / 32), dim3(32, 8)>>>(w, wp0, DIM, DIM);
        launch_gemm(actA, wp0, bias, t1, ROWS, DIM, 3 * DIM);
        add_ln_kernel<<<ROWS, 256>>>(h, t1,
                                     ln3_g + (size_t)l * DIM,
                                     ln3_b + (size_t)l * DIM, h, actA);

        // Fold interference pathways into one GEMM
        modbeff_kernel<<<DIM / 256, 256>>>(phase  + (size_t)l * 2 * DIM,
                                           path_b + (size_t)l * 2 * DIM,
                                           mod, bias);
        weff_kernel<<<(DIM * DIM / 4 + 255) / 256, 256>>>(
            path_w + (size_t)l * 2 * DIM * DIM, mod, w);
        packB_kernel<<<dim3(DIM / 32, DIM / 32), dim3(32, 8)>>>(w, wp1, DIM, DIM);
        launch_gemm(actA, wp1, bias, t1, ROWS, DIM, 3 * DIM);
        add_ln_kernel<<<ROWS, 256>>>(h, t1,
                                     ln4_g + (size_t)l * DIM,
                                     ln4_b + (size_t)l * DIM,
                                     (l == NLAYERS - 1) ? out : h,
                                     (l == NLAYERS - 1) ? (__nv_bfloat16*)nullptr
                                                        : actA);
    }
}